// round 7
// baseline (speedup 1.0000x reference)
#include <cuda_runtime.h>

#define NTOK   131072          // H*W*D
#define CCH    96
#define BB     2
#define TN     128             // tokens per tile
#define NTILE  1024            // NTOK/TN
#define NBLK   (BB*NTILE)      // 2048
#define NPART  1248            // 8*144 KV + 96 sumK
#define RS     132             // smem tile row stride (floats)
#define R4     (RS/4)
#define WS     100             // weight row stride (16B-aligned rows)

__device__ float g_partial[NBLK * NPART];
__device__ float g_red[BB * NPART];
__device__ float g_ctx[BB * 1152];
__device__ float g_p[(size_t)BB * CCH * NTOK];   // softmax(q), channel-major

typedef unsigned long long ull;

__device__ __forceinline__ ull pack2(float x, float y) {
    ull r; asm("mov.b64 %0, {%1, %2};" : "=l"(r) : "f"(x), "f"(y)); return r;
}
__device__ __forceinline__ void fma2(ull& d, ull a, ull b) {
    asm("fma.rn.f32x2 %0, %1, %2, %0;" : "+l"(d) : "l"(a), "l"(b));
}
__device__ __forceinline__ float2 unpack2(ull a) {
    float lo, hi; asm("mov.b64 {%0, %1}, %2;" : "=f"(lo), "=f"(hi) : "l"(a));
    return make_float2(lo, hi);
}

// one GEMM pass: 12 channels (og) x 2 tokens (nt) per thread, 12 ull accs
__device__ __forceinline__ void gemm_pass(const float* __restrict__ sX,
                                          const float* __restrict__ sW,
                                          int og, int nt, ull acc[12])
{
    #pragma unroll
    for (int j = 0; j < 12; j++) acc[j] = 0ull;
    #pragma unroll 2
    for (int c = 0; c < 96; c++) {
        float2 xv = *(const float2*)(sX + c * RS + nt);
        ull x0 = pack2(xv.x, xv.x), x1 = pack2(xv.y, xv.y);
        const ulonglong2* w4 = (const ulonglong2*)(sW + c * WS + og * 12);
        #pragma unroll
        for (int jj = 0; jj < 3; jj++) {
            ulonglong2 w = w4[jj];
            fma2(acc[jj * 4 + 0], w.x, x0); fma2(acc[jj * 4 + 1], w.x, x1);
            fma2(acc[jj * 4 + 2], w.y, x0); fma2(acc[jj * 4 + 3], w.y, x1);
        }
    }
}

// =====================================================================
// Kernel A: stage x tile; 3 sequential GEMM passes (k, v, q) each with
// 12 accumulators (no spills); softmax(q)->g_p; exp(k),v->smem;
// blocked KV/sumK partials. 512 threads.
// =====================================================================
__global__ void __launch_bounds__(512, 1)
qkv_kernel(const float* __restrict__ x, const float* __restrict__ Wq,
           const float* __restrict__ Wk, const float* __restrict__ Wv)
{
    extern __shared__ float sm[];
    float* sX = sm;                     // [96][RS]
    float* sK = sX + 96 * RS;           // [96][RS]
    float* sV = sK + 96 * RS;           // [96][RS]
    float* sW = sV + 96 * RS;           // [96][WS] one weight at a time

    const int tile = blockIdx.x;
    const int b    = tile >> 10;
    const int n0   = (tile & (NTILE - 1)) * TN;
    const int tid  = threadIdx.x;
    const int tg   = tid & 63;
    const int og   = tid >> 6;          // head 0..7
    const int nt   = tg * 2;

    const float* xb = x + (size_t)b * CCH * NTOK + n0;
    for (int i = tid; i < CCH * TN; i += 512) {
        int c = i >> 7, nn = i & (TN - 1);
        sX[c * RS + nn] = xb[(size_t)c * NTOK + nn];
    }
    for (int i = tid; i < CCH * CCH; i += 512)
        sW[(i % 96) * WS + (i / 96)] = Wk[i];
    __syncthreads();

    ull acc[12];

    // ---- k pass: exp(k) -> sK ----
    gemm_pass(sX, sW, og, nt, acc);
    #pragma unroll
    for (int jj = 0; jj < 3; jj++)
        #pragma unroll
        for (int jh = 0; jh < 2; jh++) {
            float2 a0 = unpack2(acc[jj * 4 + jh * 2 + 0]);   // token 0
            float2 a1 = unpack2(acc[jj * 4 + jh * 2 + 1]);   // token 1
            int o = og * 12 + jj * 4 + jh * 2;
            *(float2*)(sK + o * RS + nt)       = make_float2(__expf(a0.x), __expf(a1.x));
            *(float2*)(sK + (o + 1) * RS + nt) = make_float2(__expf(a0.y), __expf(a1.y));
        }
    __syncthreads();
    for (int i = tid; i < CCH * CCH; i += 512)
        sW[(i % 96) * WS + (i / 96)] = Wv[i];
    __syncthreads();

    // ---- v pass: v -> sV ----
    gemm_pass(sX, sW, og, nt, acc);
    #pragma unroll
    for (int jj = 0; jj < 3; jj++)
        #pragma unroll
        for (int jh = 0; jh < 2; jh++) {
            float2 a0 = unpack2(acc[jj * 4 + jh * 2 + 0]);
            float2 a1 = unpack2(acc[jj * 4 + jh * 2 + 1]);
            int o = og * 12 + jj * 4 + jh * 2;
            *(float2*)(sV + o * RS + nt)       = make_float2(a0.x, a1.x);
            *(float2*)(sV + (o + 1) * RS + nt) = make_float2(a0.y, a1.y);
        }
    __syncthreads();
    for (int i = tid; i < CCH * CCH; i += 512)
        sW[(i % 96) * WS + (i / 96)] = Wq[i];
    __syncthreads();

    // ---- q pass: softmax over head dim, store p ----
    gemm_pass(sX, sW, og, nt, acc);
    {
        float p0[12], p1[12];
        #pragma unroll
        for (int t = 0; t < 2; t++) {
            float qv[12];
            #pragma unroll
            for (int jj = 0; jj < 3; jj++)
                #pragma unroll
                for (int jh = 0; jh < 2; jh++) {
                    float2 v = unpack2(acc[jj * 4 + jh * 2 + t]);
                    qv[jj * 4 + jh * 2]     = v.x;
                    qv[jj * 4 + jh * 2 + 1] = v.y;
                }
            float m = qv[0];
            #pragma unroll
            for (int i = 1; i < 12; i++) m = fmaxf(m, qv[i]);
            float s = 0.f; float* pp = t ? p1 : p0;
            #pragma unroll
            for (int i = 0; i < 12; i++) { pp[i] = __expf(qv[i] - m); s += pp[i]; }
            float inv = 1.f / s;
            #pragma unroll
            for (int i = 0; i < 12; i++) pp[i] *= inv;
        }
        float* gp = g_p + (size_t)b * CCH * NTOK + n0 + nt;
        #pragma unroll
        for (int i = 0; i < 12; i++)
            *(float2*)(gp + (size_t)(og * 12 + i) * NTOK) = make_float2(p0[i], p1[i]);
    }
    __syncthreads();

    // ---- blocked KV / sumK partials: 72 KV tasks (4x4) + 24 sumK ----
    float* po = g_partial + (size_t)tile * NPART;
    if (tid < 72) {
        int h = tid / 9, r = tid - h * 9, db = r / 3, eb = r - db * 3;
        const float4* pk0 = (const float4*)(sK + (h * 12 + db * 4) * RS);
        const float4* pv0 = (const float4*)(sV + (h * 12 + eb * 4) * RS);
        ull a2[16];
        #pragma unroll
        for (int i = 0; i < 16; i++) a2[i] = 0ull;
        #pragma unroll 2
        for (int t = 0; t < TN / 4; t++) {
            float4 K[4], V[4];
            #pragma unroll
            for (int i = 0; i < 4; i++) { K[i] = pk0[i * R4 + t]; V[i] = pv0[i * R4 + t]; }
            ull Kxy[4], Kzw[4], Vxy[4], Vzw[4];
            #pragma unroll
            for (int i = 0; i < 4; i++) {
                Kxy[i] = pack2(K[i].x, K[i].y); Kzw[i] = pack2(K[i].z, K[i].w);
                Vxy[i] = pack2(V[i].x, V[i].y); Vzw[i] = pack2(V[i].z, V[i].w);
            }
            #pragma unroll
            for (int i = 0; i < 4; i++)
                #pragma unroll
                for (int j = 0; j < 4; j++) {
                    fma2(a2[i * 4 + j], Kxy[i], Vxy[j]);
                    fma2(a2[i * 4 + j], Kzw[i], Vzw[j]);
                }
        }
        #pragma unroll
        for (int i = 0; i < 4; i++)
            #pragma unroll
            for (int j = 0; j < 4; j++) {
                float2 v = unpack2(a2[i * 4 + j]);
                po[h * 144 + (db * 4 + i) * 12 + eb * 4 + j] = v.x + v.y;
            }
    } else if (tid < 96) {
        int c0 = (tid - 72) * 4;
        float a[4] = {0.f, 0.f, 0.f, 0.f};
        #pragma unroll 2
        for (int t = 0; t < TN / 4; t++) {
            #pragma unroll
            for (int i = 0; i < 4; i++) {
                float4 K = ((const float4*)(sK + (c0 + i) * RS))[t];
                a[i] += K.x + K.y + K.z + K.w;
            }
        }
        #pragma unroll
        for (int i = 0; i < 4; i++) po[1152 + c0 + i] = a[i];
    }
}

// ===== reduce tile partials per batch (fixed order) =====
__global__ void red_kernel()
{
    int idx = blockIdx.x * 256 + threadIdx.x;
    int b = blockIdx.y;
    if (idx >= NPART) return;
    float a = 0.f;
    const float* p = g_partial + (size_t)b * NTILE * NPART + idx;
    #pragma unroll 4
    for (int t = 0; t < NTILE; t++) a += p[(size_t)t * NPART];
    g_red[b * NPART + idx] = a;
}

// ===== context[b,h,d,e] = KV[h,d,e] / sumK[h*12+d] =====
__global__ void ctx_kernel()
{
    int gid = blockIdx.x * 256 + threadIdx.x;
    if (gid >= BB * 1152) return;
    int b = gid / 1152;
    int r = gid - b * 1152;
    int h = r / 144, d = (r % 144) / 12;
    g_ctx[gid] = g_red[b * NPART + r] / g_red[b * NPART + 1152 + h * 12 + d];
}

// =====================================================================
// Kernel C: load p tile -> attn = p @ ctx IN-PLACE -> proj GEMM.
// =====================================================================
__global__ void __launch_bounds__(256, 2)
out_kernel(const float* __restrict__ Wproj, float* __restrict__ out)
{
    extern __shared__ float sm[];
    float* sP   = sm;                   // [96][RS]
    float* sW   = sP + 96 * RS;         // [96][WS]
    float* sCtx = sW + 96 * WS;         // 1152

    const int tile = blockIdx.x;
    const int b    = tile >> 10;
    const int n0   = (tile & (NTILE - 1)) * TN;
    const int tid  = threadIdx.x;
    const int tg   = tid & 31;
    const int og   = tid >> 5;
    const int nt   = tg * 4;

    const float* gp = g_p + (size_t)b * CCH * NTOK + n0;
    for (int i = tid; i < CCH * TN; i += 256) {
        int c = i >> 7, nn = i & (TN - 1);
        sP[c * RS + nn] = gp[(size_t)c * NTOK + nn];
    }
    for (int i = tid; i < CCH * CCH; i += 256)
        sW[(i % 96) * WS + (i / 96)] = Wproj[i];
    for (int i = tid; i < 1152; i += 256) sCtx[i] = g_ctx[b * 1152 + i];
    __syncthreads();

    // attn = p @ ctx, in-place per (head, token) slice
    const ull* cx2 = (const ull*)(sCtx + og * 144);
    #pragma unroll
    for (int t = 0; t < 4; t++) {
        float pv[12];
        #pragma unroll
        for (int d = 0; d < 12; d++) pv[d] = sP[(og * 12 + d) * RS + nt + t];
        ull at[6];
        #pragma unroll
        for (int j = 0; j < 6; j++) at[j] = 0ull;
        #pragma unroll
        for (int d = 0; d < 12; d++) {
            ull pd = pack2(pv[d], pv[d]);
            #pragma unroll
            for (int j = 0; j < 6; j++) fma2(at[j], cx2[d * 6 + j], pd);
        }
        #pragma unroll
        for (int j = 0; j < 6; j++) {
            float2 v = unpack2(at[j]);
            sP[(og * 12 + 2 * j) * RS + nt + t]     = v.x;
            sP[(og * 12 + 2 * j + 1) * RS + nt + t] = v.y;
        }
    }
    __syncthreads();

    // proj GEMM
    ull ap[24];
    #pragma unroll
    for (int j = 0; j < 24; j++) ap[j] = 0ull;
    #pragma unroll 2
    for (int c = 0; c < 96; c++) {
        float4 av = *(const float4*)(sP + c * RS + nt);
        ull x0 = pack2(av.x, av.x), x1 = pack2(av.y, av.y);
        ull x2 = pack2(av.z, av.z), x3 = pack2(av.w, av.w);
        const ulonglong2* w4 = (const ulonglong2*)(sW + c * WS + og * 12);
        #pragma unroll
        for (int jj = 0; jj < 3; jj++) {
            ulonglong2 w = w4[jj];
            fma2(ap[jj * 8 + 0], w.x, x0); fma2(ap[jj * 8 + 1], w.x, x1);
            fma2(ap[jj * 8 + 2], w.x, x2); fma2(ap[jj * 8 + 3], w.x, x3);
            fma2(ap[jj * 8 + 4], w.y, x0); fma2(ap[jj * 8 + 5], w.y, x1);
            fma2(ap[jj * 8 + 6], w.y, x2); fma2(ap[jj * 8 + 7], w.y, x3);
        }
    }

    float* ob = out + (size_t)b * CCH * NTOK + n0 + nt;
    #pragma unroll
    for (int jj = 0; jj < 3; jj++)
        #pragma unroll
        for (int jh = 0; jh < 2; jh++) {
            float2 v0 = unpack2(ap[jj * 8 + jh * 4 + 0]);
            float2 v1 = unpack2(ap[jj * 8 + jh * 4 + 1]);
            float2 v2 = unpack2(ap[jj * 8 + jh * 4 + 2]);
            float2 v3 = unpack2(ap[jj * 8 + jh * 4 + 3]);
            int o = og * 12 + jj * 4 + jh * 2;
            *(float4*)(ob + (size_t)o * NTOK)       = make_float4(v0.x, v1.x, v2.x, v3.x);
            *(float4*)(ob + (size_t)(o + 1) * NTOK) = make_float4(v0.y, v1.y, v2.y, v3.y);
        }
}

extern "C" void kernel_launch(void* const* d_in, const int* in_sizes, int n_in,
                              void* d_out, int out_size)
{
    const float* x  = (const float*)d_in[0];
    const float* Wq = (const float*)d_in[1];
    const float* Wk = (const float*)d_in[2];
    const float* Wv = (const float*)d_in[3];
    const float* Wp = (const float*)d_in[4];
    float* out = (float*)d_out;

    const size_t smA = (size_t)(3 * 96 * RS + 96 * WS) * sizeof(float);   // 190,464 B
    const size_t smC = (size_t)(96 * RS + 96 * WS + 1152) * sizeof(float);
    cudaFuncSetAttribute(qkv_kernel, cudaFuncAttributeMaxDynamicSharedMemorySize, (int)smA);
    cudaFuncSetAttribute(out_kernel, cudaFuncAttributeMaxDynamicSharedMemorySize, (int)smC);

    qkv_kernel<<<NBLK, 512, smA>>>(x, Wq, Wk, Wv);
    red_kernel<<<dim3(5, BB), 256>>>();
    ctx_kernel<<<(BB * 1152 + 255) / 256, 256>>>();
    out_kernel<<<NBLK, 256, smC>>>(Wp, out);
}

// round 8
// speedup vs baseline: 1.3894x; 1.3894x over previous
#include <cuda_runtime.h>

#define NTOK   131072          // H*W*D
#define CCH    96
#define BB     2
#define TN     128             // tokens per tile
#define NTILE  1024            // NTOK/TN
#define NBLK   (BB*NTILE)      // 2048
#define NPART  1248            // 8*144 KV + 96 sumK
#define NSEG   8               // reduction segments
#define RS     132             // smem tile row stride (floats)
#define R4S    (RS/4)
#define WS     100             // weight row stride (400B: 16B-aligned rows)

__device__ float g_partial[NBLK * NPART];
__device__ float g_red1[NSEG * BB * NPART];
__device__ float g_red[BB * NPART];
__device__ float g_ctx[BB * 1152];

typedef unsigned long long ull;

__device__ __forceinline__ ull pack2(float x, float y) {
    ull r; asm("mov.b64 %0, {%1, %2};" : "=l"(r) : "f"(x), "f"(y)); return r;
}
__device__ __forceinline__ void fma2(ull& d, ull a, ull b) {
    asm("fma.rn.f32x2 %0, %1, %2, %0;" : "+l"(d) : "l"(a), "l"(b));
}
__device__ __forceinline__ float2 unpack2(ull a) {
    float lo, hi; asm("mov.b64 {%0, %1}, %2;" : "=f"(lo), "=f"(hi) : "l"(a));
    return make_float2(lo, hi);
}

// =====================================================================
// Kernel A: stage x; fused k+v GEMM (2 tok x 12 ch x 2 mats = 24 accs);
// exp(k)->sK, v->sV; blocked KV/sumK partials. 512 threads, 1 CTA.
// =====================================================================
__global__ void __launch_bounds__(512, 1)
kv_kernel(const float* __restrict__ x,
          const float* __restrict__ Wk, const float* __restrict__ Wv)
{
    extern __shared__ float sm[];
    float* sX  = sm;                    // [96][RS]
    float* sK  = sX + 96 * RS;          // [96][RS]
    float* sV  = sK + 96 * RS;          // [96][RS]
    float* sWk = sV + 96 * RS;          // [96][WS]
    float* sWv = sWk + 96 * WS;         // [96][WS]

    const int tile = blockIdx.x;
    const int b    = tile >> 10;
    const int n0   = (tile & (NTILE - 1)) * TN;
    const int tid  = threadIdx.x;
    const int tg   = tid & 63;
    const int og   = tid >> 6;          // head 0..7
    const int nt   = tg * 2;

    // stage x tile (float4 coalesced)
    const float* xb = x + (size_t)b * CCH * NTOK + n0;
    for (int i = tid; i < CCH * (TN / 4); i += 512) {
        int c = i >> 5, n4 = i & 31;    // TN/4 = 32
        ((float4*)(sX + c * RS))[n4] = ((const float4*)(xb + (size_t)c * NTOK))[n4];
    }
    for (int i = tid; i < CCH * CCH; i += 512) {
        int o = i / 96, c = i - o * 96;
        sWk[c * WS + o] = Wk[i];
        sWv[c * WS + o] = Wv[i];
    }
    __syncthreads();

    // fused k+v GEMM
    ull ak[12], av[12];
    #pragma unroll
    for (int j = 0; j < 12; j++) { ak[j] = 0ull; av[j] = 0ull; }
    #pragma unroll 2
    for (int c = 0; c < 96; c++) {
        float2 xv = *(const float2*)(sX + c * RS + nt);
        ull x0 = pack2(xv.x, xv.x), x1 = pack2(xv.y, xv.y);
        const ulonglong2* wk4 = (const ulonglong2*)(sWk + c * WS + og * 12);
        const ulonglong2* wv4 = (const ulonglong2*)(sWv + c * WS + og * 12);
        #pragma unroll
        for (int jj = 0; jj < 3; jj++) {
            ulonglong2 wk = wk4[jj], wv = wv4[jj];
            fma2(ak[jj * 4 + 0], wk.x, x0); fma2(ak[jj * 4 + 1], wk.x, x1);
            fma2(ak[jj * 4 + 2], wk.y, x0); fma2(ak[jj * 4 + 3], wk.y, x1);
            fma2(av[jj * 4 + 0], wv.x, x0); fma2(av[jj * 4 + 1], wv.x, x1);
            fma2(av[jj * 4 + 2], wv.y, x0); fma2(av[jj * 4 + 3], wv.y, x1);
        }
    }

    // write exp(k) -> sK, v -> sV
    #pragma unroll
    for (int jj = 0; jj < 3; jj++)
        #pragma unroll
        for (int s = 0; s < 2; s++) {
            float2 k0 = unpack2(ak[jj * 4 + s * 2 + 0]);   // token nt
            float2 k1 = unpack2(ak[jj * 4 + s * 2 + 1]);   // token nt+1
            float2 v0 = unpack2(av[jj * 4 + s * 2 + 0]);
            float2 v1 = unpack2(av[jj * 4 + s * 2 + 1]);
            int o = og * 12 + jj * 4 + s * 2;
            *(float2*)(sK + o * RS + nt)       = make_float2(__expf(k0.x), __expf(k1.x));
            *(float2*)(sK + (o + 1) * RS + nt) = make_float2(__expf(k0.y), __expf(k1.y));
            *(float2*)(sV + o * RS + nt)       = make_float2(v0.x, v1.x);
            *(float2*)(sV + (o + 1) * RS + nt) = make_float2(v0.y, v1.y);
        }
    __syncthreads();

    // blocked KV / sumK partials: 72 KV tasks (4x4) + 24 sumK tasks
    float* po = g_partial + (size_t)tile * NPART;
    if (tid < 72) {
        int h = tid / 9, r = tid - h * 9, db = r / 3, eb = r - db * 3;
        const float4* pk0 = (const float4*)(sK + (h * 12 + db * 4) * RS);
        const float4* pv0 = (const float4*)(sV + (h * 12 + eb * 4) * RS);
        ull a2[16];
        #pragma unroll
        for (int i = 0; i < 16; i++) a2[i] = 0ull;
        #pragma unroll 2
        for (int t = 0; t < TN / 4; t++) {
            float4 K[4], V[4];
            #pragma unroll
            for (int i = 0; i < 4; i++) { K[i] = pk0[i * R4S + t]; V[i] = pv0[i * R4S + t]; }
            ull Kxy[4], Kzw[4], Vxy[4], Vzw[4];
            #pragma unroll
            for (int i = 0; i < 4; i++) {
                Kxy[i] = pack2(K[i].x, K[i].y); Kzw[i] = pack2(K[i].z, K[i].w);
                Vxy[i] = pack2(V[i].x, V[i].y); Vzw[i] = pack2(V[i].z, V[i].w);
            }
            #pragma unroll
            for (int i = 0; i < 4; i++)
                #pragma unroll
                for (int j = 0; j < 4; j++) {
                    fma2(a2[i * 4 + j], Kxy[i], Vxy[j]);
                    fma2(a2[i * 4 + j], Kzw[i], Vzw[j]);
                }
        }
        #pragma unroll
        for (int i = 0; i < 4; i++)
            #pragma unroll
            for (int j = 0; j < 4; j++) {
                float2 v = unpack2(a2[i * 4 + j]);
                po[h * 144 + (db * 4 + i) * 12 + eb * 4 + j] = v.x + v.y;
            }
    } else if (tid < 96) {
        int c0 = (tid - 72) * 4;
        float a[4] = {0.f, 0.f, 0.f, 0.f};
        #pragma unroll 2
        for (int t = 0; t < TN / 4; t++)
            #pragma unroll
            for (int i = 0; i < 4; i++) {
                float4 K = ((const float4*)(sK + (c0 + i) * RS))[t];
                a[i] += K.x + K.y + K.z + K.w;
            }
        #pragma unroll
        for (int i = 0; i < 4; i++) po[1152 + c0 + i] = a[i];
    }
}

// ===== stage-1 reduce: 8 segments of 128 tiles each =====
__global__ void red1_kernel()
{
    int idx = blockIdx.x * 256 + threadIdx.x;
    int b = blockIdx.y, seg = blockIdx.z;
    if (idx >= NPART) return;
    float a = 0.f;
    const float* p = g_partial +
        ((size_t)(b * NTILE + seg * (NTILE / NSEG))) * NPART + idx;
    #pragma unroll 8
    for (int t = 0; t < NTILE / NSEG; t++) a += p[(size_t)t * NPART];
    g_red1[(seg * BB + b) * NPART + idx] = a;
}

// ===== stage-2 reduce: sum the 8 segments (fixed order) =====
__global__ void red2_kernel()
{
    int gid = blockIdx.x * 256 + threadIdx.x;
    if (gid >= BB * NPART) return;
    int b = gid / NPART, idx = gid - b * NPART;
    float a = 0.f;
    #pragma unroll
    for (int s = 0; s < NSEG; s++) a += g_red1[(s * BB + b) * NPART + idx];
    g_red[gid] = a;
}

// ===== context[b,h,d,e] = KV[h,d,e] / sumK[h*12+d] =====
__global__ void ctx_kernel()
{
    int gid = blockIdx.x * 256 + threadIdx.x;
    if (gid >= BB * 1152) return;
    int b = gid / 1152;
    int r = gid - b * 1152;
    int h = r / 144, d = (r % 144) / 12;
    g_ctx[gid] = g_red[b * NPART + r] / g_red[b * NPART + 1152 + h * 12 + d];
}

// =====================================================================
// Kernel C: stage x -> q GEMM -> softmax + attn (in-place into x tile)
// -> proj GEMM -> out. 256 threads, 4 tok x 12 ch, 2 CTAs/SM.
// =====================================================================
__global__ void __launch_bounds__(256, 2)
out2_kernel(const float* __restrict__ x, const float* __restrict__ Wq,
            const float* __restrict__ Wproj, float* __restrict__ out)
{
    extern __shared__ float sm[];
    float* sX   = sm;                   // [96][RS]: x, then attn in-place
    float* sW   = sX + 96 * RS;         // [96][WS]: Wq, then Wproj
    float* sCtx = sW + 96 * WS;         // 1152

    const int tile = blockIdx.x;
    const int b    = tile >> 10;
    const int n0   = (tile & (NTILE - 1)) * TN;
    const int tid  = threadIdx.x;
    const int tg   = tid & 31;
    const int og   = tid >> 5;
    const int nt   = tg * 4;

    const float* xb = x + (size_t)b * CCH * NTOK + n0;
    for (int i = tid; i < CCH * (TN / 4); i += 256) {
        int c = i >> 5, n4 = i & 31;
        ((float4*)(sX + c * RS))[n4] = ((const float4*)(xb + (size_t)c * NTOK))[n4];
    }
    for (int i = tid; i < CCH * CCH; i += 256) {
        int o = i / 96, c = i - o * 96;
        sW[c * WS + o] = Wq[i];
    }
    for (int i = tid; i < 1152; i += 256) sCtx[i] = g_ctx[b * 1152 + i];
    __syncthreads();

    // ---- q GEMM: 24 accs [jj][s(w.x/w.y)][t] ----
    ull aq[24];
    #pragma unroll
    for (int j = 0; j < 24; j++) aq[j] = 0ull;
    #pragma unroll 2
    for (int c = 0; c < 96; c++) {
        float4 xv = *(const float4*)(sX + c * RS + nt);
        ull x0 = pack2(xv.x, xv.x), x1 = pack2(xv.y, xv.y);
        ull x2 = pack2(xv.z, xv.z), x3 = pack2(xv.w, xv.w);
        const ulonglong2* w4 = (const ulonglong2*)(sW + c * WS + og * 12);
        #pragma unroll
        for (int jj = 0; jj < 3; jj++) {
            ulonglong2 w = w4[jj];
            fma2(aq[jj * 8 + 0], w.x, x0); fma2(aq[jj * 8 + 1], w.x, x1);
            fma2(aq[jj * 8 + 2], w.x, x2); fma2(aq[jj * 8 + 3], w.x, x3);
            fma2(aq[jj * 8 + 4], w.y, x0); fma2(aq[jj * 8 + 5], w.y, x1);
            fma2(aq[jj * 8 + 6], w.y, x2); fma2(aq[jj * 8 + 7], w.y, x3);
        }
    }
    __syncthreads();    // all reads of sX (x) and sW (Wq) complete

    // reload sW with Wproj while softmax/attn proceed
    for (int i = tid; i < CCH * CCH; i += 256) {
        int o = i / 96, c = i - o * 96;
        sW[c * WS + o] = Wproj[i];
    }

    // ---- softmax + attn per token, write into sX in-place ----
    const ull* cx2 = (const ull*)(sCtx + og * 144);   // [12 d][6 e-pairs]
    #pragma unroll
    for (int t = 0; t < 4; t++) {
        float qv[12];
        #pragma unroll
        for (int jj = 0; jj < 3; jj++)
            #pragma unroll
            for (int s = 0; s < 2; s++) {
                float2 v = unpack2(aq[jj * 8 + s * 4 + t]);
                qv[jj * 4 + s * 2]     = v.x;
                qv[jj * 4 + s * 2 + 1] = v.y;
            }
        float m = qv[0];
        #pragma unroll
        for (int i = 1; i < 12; i++) m = fmaxf(m, qv[i]);
        float p[12]; float sum = 0.f;
        #pragma unroll
        for (int i = 0; i < 12; i++) { p[i] = __expf(qv[i] - m); sum += p[i]; }
        float inv = 1.f / sum;

        ull at[6];
        #pragma unroll
        for (int j = 0; j < 6; j++) at[j] = 0ull;
        #pragma unroll
        for (int d = 0; d < 12; d++) {
            ull pd = pack2(p[d], p[d]);
            #pragma unroll
            for (int j = 0; j < 6; j++) fma2(at[j], cx2[d * 6 + j], pd);
        }
        #pragma unroll
        for (int j = 0; j < 6; j++) {
            float2 v = unpack2(at[j]);
            sX[(og * 12 + 2 * j) * RS + nt + t]     = v.x * inv;
            sX[(og * 12 + 2 * j + 1) * RS + nt + t] = v.y * inv;
        }
    }
    __syncthreads();    // attn writes + Wproj load complete

    // ---- proj GEMM ----
    ull ap[24];
    #pragma unroll
    for (int j = 0; j < 24; j++) ap[j] = 0ull;
    #pragma unroll 2
    for (int c = 0; c < 96; c++) {
        float4 av = *(const float4*)(sX + c * RS + nt);
        ull x0 = pack2(av.x, av.x), x1 = pack2(av.y, av.y);
        ull x2 = pack2(av.z, av.z), x3 = pack2(av.w, av.w);
        const ulonglong2* w4 = (const ulonglong2*)(sW + c * WS + og * 12);
        #pragma unroll
        for (int jj = 0; jj < 3; jj++) {
            ulonglong2 w = w4[jj];
            fma2(ap[jj * 8 + 0], w.x, x0); fma2(ap[jj * 8 + 1], w.x, x1);
            fma2(ap[jj * 8 + 2], w.x, x2); fma2(ap[jj * 8 + 3], w.x, x3);
            fma2(ap[jj * 8 + 4], w.y, x0); fma2(ap[jj * 8 + 5], w.y, x1);
            fma2(ap[jj * 8 + 6], w.y, x2); fma2(ap[jj * 8 + 7], w.y, x3);
        }
    }

    float* ob = out + (size_t)b * CCH * NTOK + n0 + nt;
    #pragma unroll
    for (int jj = 0; jj < 3; jj++)
        #pragma unroll
        for (int s = 0; s < 2; s++) {
            float2 v0 = unpack2(ap[jj * 8 + s * 4 + 0]);
            float2 v1 = unpack2(ap[jj * 8 + s * 4 + 1]);
            float2 v2 = unpack2(ap[jj * 8 + s * 4 + 2]);
            float2 v3 = unpack2(ap[jj * 8 + s * 4 + 3]);
            int o = og * 12 + jj * 4 + s * 2;
            *(float4*)(ob + (size_t)o * NTOK)       = make_float4(v0.x, v1.x, v2.x, v3.x);
            *(float4*)(ob + (size_t)(o + 1) * NTOK) = make_float4(v0.y, v1.y, v2.y, v3.y);
        }
}

extern "C" void kernel_launch(void* const* d_in, const int* in_sizes, int n_in,
                              void* d_out, int out_size)
{
    const float* x  = (const float*)d_in[0];
    const float* Wq = (const float*)d_in[1];
    const float* Wk = (const float*)d_in[2];
    const float* Wv = (const float*)d_in[3];
    const float* Wp = (const float*)d_in[4];
    float* out = (float*)d_out;

    const size_t smA = (size_t)(3 * 96 * RS + 2 * 96 * WS) * sizeof(float);   // 228,864 B
    const size_t smC = (size_t)(96 * RS + 96 * WS + 1152) * sizeof(float);    //  93,696 B
    cudaFuncSetAttribute(kv_kernel,   cudaFuncAttributeMaxDynamicSharedMemorySize, (int)smA);
    cudaFuncSetAttribute(out2_kernel, cudaFuncAttributeMaxDynamicSharedMemorySize, (int)smC);

    kv_kernel<<<NBLK, 512, smA>>>(x, Wk, Wv);
    red1_kernel<<<dim3(5, BB, NSEG), 256>>>();
    red2_kernel<<<(BB * NPART + 255) / 256, 256>>>();
    ctx_kernel<<<(BB * 1152 + 255) / 256, 256>>>();
    out2_kernel<<<NBLK, 256, smC>>>(x, Wq, Wp, out);
}